// round 15
// baseline (speedup 1.0000x reference)
#include <cuda_runtime.h>
#include <math.h>
#include <stdint.h>

// ---------------- problem constants (fixed shapes) ----------------
#define NN    20000
#define TT    8
#define DSX   16
#define DDIM  8
#define EE    320000
#define HLX   128
#define GHX   4
#define GCX   128
#define HCX   512
#define EMBX  64
#define IN1X  (DSX + HLX)       // 144
#define ETOT  (EE + NN)
#define TNN   (TT * NN)         // 160000
#define XLD   (2 * HCX)         // 1024 combined xl|xr row stride

// ---------------- scratch ----------------
__device__ float g_hs[TT * NN * HLX];        // tf32-rounded h states (natural layout)
__device__ float g_c[NN * HLX];
__device__ float g_gatesx[TNN * 4 * HLX];    // PACKED gate layout
__device__ float g_AB[(size_t)TNN * XLD];
__device__ float g_bufC[TNN * HCX];
__device__ float g_bufD[TNN * HCX];
__device__ float g_xscat[NN * XLD];
__device__ float g_dynt[TNN * DDIM];
__device__ float g_xst[NN * DSX];
__device__ float g_WcatS[XLD * DSX];
__device__ float g_WcatD[XLD * HLX];
__device__ float g_Wcat2[XLD * HCX];
__device__ float g_Wih[4 * HLX * DDIM];      // PACKED rows
__device__ float g_Whh[4 * HLX * HLX];       // PACKED rows
__device__ float g_Wpt[EMBX * HCX];
__device__ float g_bsum[4 * HLX];            // PACKED
__device__ float g_sum[TT * HCX];
__device__ float g_sumsq[TT * HCX];
__device__ float g_scale[TT * HCX];
__device__ float g_shift[TT * HCX];
__device__ int   g_deg[NN];
__device__ int   g_off[NN + 1];
__device__ int   g_cursor[NN];
__device__ int   g_csr[ETOT];

__device__ __forceinline__ uint32_t f2tf(float f) {
    uint32_t u;
    asm("cvt.rna.tf32.f32 %0, %1;" : "=r"(u) : "f"(f));
    return u;
}
__device__ __forceinline__ float f2tff(float f) { return __uint_as_float(f2tf(f)); }

// packed-row -> original-row map for LSTM gate interleave:
// packed pr = 32*(j/8) + 8*g + (j%8)  <->  orig = g*128 + j
__device__ __forceinline__ int lstm_unpack(int pr) {
    int grp = pr >> 5, wi = pr & 31, gg = wi >> 3, u = wi & 7;
    return gg * HLX + (grp * 8 + u);
}

// ---------------- fused setup ----------------
__global__ void setup_kernel(const float* __restrict__ b_ih, const float* __restrict__ b_hh,
                             const float* __restrict__ Wl1, const float* __restrict__ Wr1,
                             const float* __restrict__ Wl2, const float* __restrict__ Wr2,
                             const float* __restrict__ W_ih, const float* __restrict__ W_hh,
                             const float* __restrict__ Wp)
{
    int i = blockIdx.x * blockDim.x + threadIdx.x;
    if (i < 4 * HLX) {
        int orig = lstm_unpack(i);
        g_bsum[i] = b_ih[orig] + b_hh[orig];
    }
    if (i < NN) g_deg[i] = 1;           // self loop
    if (i < TT * HCX) { g_sum[i] = 0.f; g_sumsq[i] = 0.f; }
    if (i < 4 * HLX * DDIM) {
        int r = i / DDIM, k = i % DDIM;
        g_Wih[i] = f2tff(W_ih[(size_t)lstm_unpack(r) * DDIM + k]);
    }
    if (i < 4 * HLX * HLX) {
        int r = i / HLX, k = i % HLX;
        g_Whh[i] = f2tff(W_hh[(size_t)lstm_unpack(r) * HLX + k]);
    }
    if (i < EMBX * HCX)      g_Wpt[i] = f2tff(Wp[i]);
    if (i < XLD * IN1X) {
        int j = i / IN1X, k = i % IN1X;
        const float* W = (j < HCX) ? Wl1 : Wr1;
        int jj = j & (HCX - 1);
        float v = f2tff(W[(size_t)jj * IN1X + k]);
        if (k < DSX) g_WcatS[j * DSX + k] = v;
        else         g_WcatD[j * HLX + (k - DSX)] = v;
    }
    if (i < XLD * HCX) {
        int j = i / HCX, k = i % HCX;
        g_Wcat2[i] = f2tff((j < HCX) ? Wl2[(size_t)j * HCX + k]
                                     : Wr2[(size_t)(j - HCX) * HCX + k]);
    }
}

__global__ void cvt_inputs_kernel(const float* __restrict__ dyn, const float* __restrict__ xs) {
    int i = blockIdx.x * blockDim.x + threadIdx.x;
    if (i < TNN * DDIM) g_dynt[i] = f2tff(dyn[i]);
    if (i < NN * DSX)   g_xst[i]  = f2tff(xs[i]);
}

__global__ void count_kernel(const int* __restrict__ ei) {
    int i = blockIdx.x * blockDim.x + threadIdx.x;
    if (i < EE) atomicAdd(&g_deg[ei[EE + i]], 1);
}

__global__ void scan_kernel() {
    __shared__ int s[1024];
    const int t = threadIdx.x;
    const int CH = (NN + 1023) / 1024;
    int beg = t * CH;
    int end = beg + CH; if (end > NN) end = NN;
    int sum = 0;
    for (int i = beg; i < end; i++) sum += g_deg[i];
    int v = sum;
    s[t] = v;
    __syncthreads();
    for (int off = 1; off < 1024; off <<= 1) {
        int add = (t >= off) ? s[t - off] : 0;
        __syncthreads();
        v += add;
        s[t] = v;
        __syncthreads();
    }
    int run = (t == 0) ? 0 : s[t - 1];
    for (int i = beg; i < end; i++) { g_off[i] = run; g_cursor[i] = run; run += g_deg[i]; }
    if (t == 1023) g_off[NN] = s[1023];
}

__global__ void fill_kernel(const int* __restrict__ ei) {
    int i = blockIdx.x * blockDim.x + threadIdx.x;
    if (i < EE) {
        int s = ei[i];
        int d = ei[EE + i];
        int pos = atomicAdd(&g_cursor[d], 1);
        g_csr[pos] = s;
    } else if (i < ETOT) {
        int d = i - EE;
        int pos = atomicAdd(&g_cursor[d], 1);
        g_csr[pos] = d;
    }
}

// ---------------- tf32 tensor-core GEMM with cp.async pipeline ------------
#define GBM 128
#define GBK 16
#define SKP 20

__device__ __forceinline__ void cp16(uint32_t saddr, const float* g, bool pred) {
    int bytes = pred ? 16 : 0;
    asm volatile("cp.async.cg.shared.global [%0], [%1], 16, %2;\n"
                 :: "r"(saddr), "l"(g), "r"(bytes));
}

__device__ __forceinline__ void mma_tf32(float c[4], uint32_t a0, uint32_t a1,
                                         uint32_t a2, uint32_t a3,
                                         uint32_t b0, uint32_t b1)
{
    asm volatile(
        "mma.sync.aligned.m16n8k8.row.col.f32.tf32.tf32.f32 "
        "{%0,%1,%2,%3}, {%4,%5,%6,%7}, {%8,%9}, {%0,%1,%2,%3};\n"
        : "+f"(c[0]), "+f"(c[1]), "+f"(c[2]), "+f"(c[3])
        : "r"(a0), "r"(a1), "r"(a2), "r"(a3), "r"(b0), "r"(b1));
}

__device__ __forceinline__ float sigm(float x) { return 1.f / (1.f + __expf(-x)); }

// LSTMEPI: 0 = normal C store; 1 = fused LSTM gate epilogue (TBN==128 only)
template<int TBN, int LSTMEPI>
__global__ __launch_bounds__(256)
void gemm_tc_kernel(int M, int Ncols, int K,
                    const float* __restrict__ A, int lda,
                    const float* __restrict__ B, int ldb,
                    const float* __restrict__ bias,
                    const float* __restrict__ addmat, int addld,
                    float* __restrict__ C, int ldc, int oproj, int tstep)
{
    constexpr int WROW = (TBN == 128) ? 2 : 4;
    constexpr int MT   = (GBM / WROW) / 16;

    __shared__ float As[2][GBM][SKP];
    __shared__ float Bs[2][TBN][SKP];

    const int ktiles = (K + GBK - 1) / GBK;
    const int tid = threadIdx.x;
    const int brow = blockIdx.x * GBM;
    const int bcol = blockIdx.y * TBN;
    const int lane = tid & 31;
    const int warp = tid >> 5;
    const int g    = lane >> 2;
    const int tig  = lane & 3;
    const int wm   = warp % WROW;
    const int wn   = warp / WROW;

    const int arow = tid >> 2;
    const int kq   = (tid & 3) * 4;

    uint32_t sA0 = (uint32_t)__cvta_generic_to_shared(&As[0][arow][kq]);
    uint32_t sA1 = (uint32_t)__cvta_generic_to_shared(&As[0][arow + 64][kq]);
    uint32_t sB0 = (uint32_t)__cvta_generic_to_shared(&Bs[0][arow][kq]);
    uint32_t sB1 = (TBN == 128) ? (uint32_t)__cvta_generic_to_shared(&Bs[0][arow + 64][kq]) : 0u;
    const uint32_t aStride = (uint32_t)(GBM * SKP * 4);
    const uint32_t bStride = (uint32_t)(TBN * SKP * 4);

    float acc[MT][4][4];
#pragma unroll
    for (int mt = 0; mt < MT; mt++)
#pragma unroll
        for (int nt = 0; nt < 4; nt++)
#pragma unroll
            for (int i = 0; i < 4; i++) acc[mt][nt][i] = 0.f;

    auto issue = [&](int kt) {
        const int buf = kt & 1;
        const int k0 = kt * GBK + kq;
        const bool kok = k0 < K;
        const int kc = kok ? k0 : 0;
        {
            int r = brow + arow;
            bool p = (r < M) && kok;
            cp16(sA0 + buf * aStride, A + (size_t)(p ? r : 0) * lda + kc, p);
        }
        {
            int r = brow + arow + 64;
            bool p = (r < M) && kok;
            cp16(sA1 + buf * aStride, A + (size_t)(p ? r : 0) * lda + kc, p);
        }
        {
            int c = bcol + arow;
            bool p = (c < Ncols) && kok;
            cp16(sB0 + buf * bStride, B + (size_t)(p ? c : 0) * ldb + kc, p);
        }
        if (TBN == 128) {
            int c = bcol + arow + 64;
            bool p = (c < Ncols) && kok;
            cp16(sB1 + buf * bStride, B + (size_t)(p ? c : 0) * ldb + kc, p);
        }
        asm volatile("cp.async.commit_group;\n" ::: "memory");
    };

    issue(0);
    if (ktiles > 1) issue(1);

    for (int kt = 0; kt < ktiles; kt++) {
        if (kt + 1 < ktiles) asm volatile("cp.async.wait_group 1;\n" ::: "memory");
        else                 asm volatile("cp.async.wait_group 0;\n" ::: "memory");
        __syncthreads();

        const int buf = kt & 1;
#pragma unroll
        for (int ks = 0; ks < 2; ks++) {
            const int kb = ks * 8;
            uint32_t af[MT][4], bf[4][2];
#pragma unroll
            for (int mt = 0; mt < MT; mt++) {
                int r0 = wm * (GBM / WROW) + mt * 16 + g;
                af[mt][0] = __float_as_uint(As[buf][r0    ][kb + tig]);
                af[mt][1] = __float_as_uint(As[buf][r0 + 8][kb + tig]);
                af[mt][2] = __float_as_uint(As[buf][r0    ][kb + tig + 4]);
                af[mt][3] = __float_as_uint(As[buf][r0 + 8][kb + tig + 4]);
            }
#pragma unroll
            for (int nt = 0; nt < 4; nt++) {
                int cb = wn * 32 + nt * 8 + g;
                bf[nt][0] = __float_as_uint(Bs[buf][cb][kb + tig]);
                bf[nt][1] = __float_as_uint(Bs[buf][cb][kb + tig + 4]);
            }
#pragma unroll
            for (int mt = 0; mt < MT; mt++)
#pragma unroll
                for (int nt = 0; nt < 4; nt++)
                    mma_tf32(acc[mt][nt], af[mt][0], af[mt][1], af[mt][2], af[mt][3],
                             bf[nt][0], bf[nt][1]);
        }
        __syncthreads();
        if (kt + 2 < ktiles) issue(kt + 2);
    }

    if (LSTMEPI) {
        // fused LSTM gate epilogue: packed cols -> nt is the gate index.
        // thread holds gates 0..3 of units u = 2tig, 2tig+1 (group bcol/32+wn)
        // for rows gr0, gr0+8.
        const int grp = (bcol >> 5) + wn;
#pragma unroll
        for (int mt = 0; mt < MT; mt++) {
            int r0 = brow + wm * (GBM / WROW) + mt * 16 + g;
#pragma unroll
            for (int rr = 0; rr < 2; rr++) {
                int row = r0 + rr * 8;
                if (row >= M) continue;
                const float* gxr = g_gatesx + ((size_t)row * TT + tstep) * (4 * HLX)
                                 + grp * 32;
#pragma unroll
                for (int uu = 0; uu < 2; uu++) {
                    int sel = rr * 2 + uu;
                    int uc  = 2 * tig + uu;
                    float vi = acc[mt][0][sel] + gxr[uc];
                    float vf = acc[mt][1][sel] + gxr[8 + uc];
                    float vg = acc[mt][2][sel] + gxr[16 + uc];
                    float vo = acc[mt][3][sel] + gxr[24 + uc];
                    int j = grp * 8 + uc;
                    size_t ci = (size_t)row * HLX + j;
                    float c = sigm(vf) * g_c[ci] + sigm(vi) * tanhf(vg);
                    g_c[ci] = c;
                    g_hs[(size_t)tstep * NN * HLX + ci] = f2tff(sigm(vo) * tanhf(c));
                }
            }
        }
        return;
    }

#pragma unroll
    for (int mt = 0; mt < MT; mt++) {
        int gr0 = brow + wm * (GBM / WROW) + mt * 16 + g;
        int gr1 = gr0 + 8;
#pragma unroll
        for (int nt = 0; nt < 4; nt++) {
            int gc = bcol + wn * 32 + nt * 8 + 2 * tig;
            if (gc >= Ncols) continue;
            float bx = bias ? bias[gc]     : 0.f;
            float by = bias ? bias[gc + 1] : 0.f;
            if (gr0 < M) {
                float ax = bx, ay = by;
                if (addmat) {
                    const float* ad = addmat + (size_t)(gr0 % NN) * addld + gc;
                    ax += ad[0]; ay += ad[1];
                }
                float2 v = make_float2(acc[mt][nt][0] + ax, acc[mt][nt][1] + ay);
                size_t off = oproj ? ((size_t)(gr0 % NN) * (TT * EMBX) + (gr0 / NN) * EMBX + gc)
                                   : ((size_t)gr0 * ldc + gc);
                *reinterpret_cast<float2*>(C + off) = v;
            }
            if (gr1 < M) {
                float ax = bx, ay = by;
                if (addmat) {
                    const float* ad = addmat + (size_t)(gr1 % NN) * addld + gc;
                    ax += ad[0]; ay += ad[1];
                }
                float2 v = make_float2(acc[mt][nt][2] + ax, acc[mt][nt][3] + ay);
                size_t off = oproj ? ((size_t)(gr1 % NN) * (TT * EMBX) + (gr1 / NN) * EMBX + gc)
                                   : ((size_t)gr1 * ldc + gc);
                *reinterpret_cast<float2*>(C + off) = v;
            }
        }
    }
}

// ---------------- projection GEMM: register-staged, BN+relu fused on A ----
__global__ __launch_bounds__(256)
void gemm_proj_kernel(int M, int Ncols, int K,
                      const float* __restrict__ A, int lda,
                      const float* __restrict__ B, int ldb,
                      const float* __restrict__ bias,
                      float* __restrict__ C)
{
    constexpr int TBN = 64, WROW = 4, MT = 2;
    __shared__ uint32_t As[2][GBM][SKP];
    __shared__ uint32_t Bs[2][TBN][SKP];

    const int ktiles = K / GBK;
    const int tid = threadIdx.x;
    const int brow = blockIdx.x * GBM;
    const int bcol = 0;
    const int lane = tid & 31;
    const int warp = tid >> 5;
    const int g    = lane >> 2;
    const int tig  = lane & 3;
    const int wm   = warp % WROW;
    const int wn   = warp / WROW;

    const int arow = tid >> 2;
    const int kq   = (tid & 3) * 4;

    float acc[MT][4][4];
#pragma unroll
    for (int mt = 0; mt < MT; mt++)
#pragma unroll
        for (int nt = 0; nt < 4; nt++)
#pragma unroll
            for (int i = 0; i < 4; i++) acc[mt][nt][i] = 0.f;

    auto fetchA = [&](int r, int gk) -> float4 {
        float4 z = make_float4(0.f, 0.f, 0.f, 0.f);
        if (r >= M) return z;
        float4 v = *reinterpret_cast<const float4*>(A + (size_t)r * lda + gk);
        int t = r / NN;
        const float* sc = g_scale + t * HCX + gk;
        const float* sh = g_shift + t * HCX + gk;
        v.x = f2tff(fmaxf(0.f, v.x * sc[0] + sh[0]));
        v.y = f2tff(fmaxf(0.f, v.y * sc[1] + sh[1]));
        v.z = f2tff(fmaxf(0.f, v.z * sc[2] + sh[2]));
        v.w = f2tff(fmaxf(0.f, v.w * sc[3] + sh[3]));
        return v;
    };
    auto fetchB = [&](int c, int gk) -> float4 {
        if (c >= Ncols) return make_float4(0.f, 0.f, 0.f, 0.f);
        return *reinterpret_cast<const float4*>(B + (size_t)c * ldb + gk);
    };

    float4 rA0 = fetchA(brow + arow,      kq);
    float4 rA1 = fetchA(brow + arow + 64, kq);
    float4 rB0 = fetchB(bcol + arow,      kq);

    for (int kt = 0; kt < ktiles; kt++) {
        const int buf = kt & 1;
        As[buf][arow     ][kq+0] = __float_as_uint(rA0.x);
        As[buf][arow     ][kq+1] = __float_as_uint(rA0.y);
        As[buf][arow     ][kq+2] = __float_as_uint(rA0.z);
        As[buf][arow     ][kq+3] = __float_as_uint(rA0.w);
        As[buf][arow + 64][kq+0] = __float_as_uint(rA1.x);
        As[buf][arow + 64][kq+1] = __float_as_uint(rA1.y);
        As[buf][arow + 64][kq+2] = __float_as_uint(rA1.z);
        As[buf][arow + 64][kq+3] = __float_as_uint(rA1.w);
        if (arow < TBN) {
            Bs[buf][arow][kq+0] = __float_as_uint(rB0.x);
            Bs[buf][arow][kq+1] = __float_as_uint(rB0.y);
            Bs[buf][arow][kq+2] = __float_as_uint(rB0.z);
            Bs[buf][arow][kq+3] = __float_as_uint(rB0.w);
        }
        __syncthreads();

        if (kt + 1 < ktiles) {
            int k0 = (kt + 1) * GBK;
            rA0 = fetchA(brow + arow,      k0 + kq);
            rA1 = fetchA(brow + arow + 64, k0 + kq);
            rB0 = fetchB(bcol + arow,      k0 + kq);
        }

#pragma unroll
        for (int ks = 0; ks < 2; ks++) {
            const int kb = ks * 8;
            uint32_t af[MT][4], bf[4][2];
#pragma unroll
            for (int mt = 0; mt < MT; mt++) {
                int r0 = wm * 32 + mt * 16 + g;
                af[mt][0] = As[buf][r0    ][kb + tig];
                af[mt][1] = As[buf][r0 + 8][kb + tig];
                af[mt][2] = As[buf][r0    ][kb + tig + 4];
                af[mt][3] = As[buf][r0 + 8][kb + tig + 4];
            }
#pragma unroll
            for (int nt = 0; nt < 4; nt++) {
                int cb = wn * 32 + nt * 8 + g;
                bf[nt][0] = Bs[buf][cb][kb + tig];
                bf[nt][1] = Bs[buf][cb][kb + tig + 4];
            }
#pragma unroll
            for (int mt = 0; mt < MT; mt++)
#pragma unroll
                for (int nt = 0; nt < 4; nt++)
                    mma_tf32(acc[mt][nt], af[mt][0], af[mt][1], af[mt][2], af[mt][3],
                             bf[nt][0], bf[nt][1]);
        }
        __syncthreads();
    }

#pragma unroll
    for (int mt = 0; mt < MT; mt++) {
        int gr0 = brow + wm * 32 + mt * 16 + g;
        int gr1 = gr0 + 8;
#pragma unroll
        for (int nt = 0; nt < 4; nt++) {
            int gc = wn * 32 + nt * 8 + 2 * tig;
            float bx = bias[gc], by = bias[gc + 1];
            if (gr0 < M) {
                float2 v = make_float2(acc[mt][nt][0] + bx, acc[mt][nt][1] + by);
                size_t off = (size_t)(gr0 % NN) * (TT * EMBX) + (gr0 / NN) * EMBX + gc;
                *reinterpret_cast<float2*>(C + off) = v;
            }
            if (gr1 < M) {
                float2 v = make_float2(acc[mt][nt][2] + bx, acc[mt][nt][3] + by);
                size_t off = (size_t)(gr1 % NN) * (TT * EMBX) + (gr1 / NN) * EMBX + gc;
                *reinterpret_cast<float2*>(C + off) = v;
            }
        }
    }
}

// ---------------- LSTM t=0 gate pass (reads PACKED gatesx) ----------------
__global__ void lstm_gate0_kernel() {
    int i = blockIdx.x * blockDim.x + threadIdx.x;
    if (i >= NN * HLX) return;
    int n = i / HLX, j = i % HLX;
    const float* gx = g_gatesx + ((size_t)n * TT) * (4 * HLX)
                    + 32 * (j >> 3) + (j & 7);
    float gi = sigm(gx[0]);
    float gg = tanhf(gx[16]);
    float go = sigm(gx[24]);
    float c = gi * gg;                  // c_old = 0 (forget term vanishes)
    g_c[i] = c;
    g_hs[i] = f2tff(go * tanhf(c));
}

// ---------------- GATv2 aggregation (batched over t, 2-way ILP) ----------
__device__ __forceinline__ float4 leaky_add(float4 a, const float4& b) {
    float4 e;
    e.x = a.x + b.x; e.x = e.x > 0.f ? e.x : 0.2f * e.x;
    e.y = a.y + b.y; e.y = e.y > 0.f ? e.y : 0.2f * e.y;
    e.z = a.z + b.z; e.z = e.z > 0.f ? e.z : 0.2f * e.z;
    e.w = a.w + b.w; e.w = e.w > 0.f ? e.w : 0.2f * e.w;
    return e;
}

__global__ void gat_kernel(const float* __restrict__ xlxr,
                           const float* __restrict__ att,
                           const float* __restrict__ bias,
                           float* __restrict__ out)
{
    const int d = blockIdx.x;
    const int t = blockIdx.y;
    const int w = threadIdx.x >> 5;
    const int lane = threadIdx.x & 31;
    const int base = w * GCX + lane * 4;
    const size_t tbase = (size_t)t * NN;

    const float4 xrv = *reinterpret_cast<const float4*>(xlxr + (tbase + d) * XLD + HCX + base);
    const float4 av  = *reinterpret_cast<const float4*>(att + w * GCX + lane * 4);

    float mA = -1e30f, dA = 0.f, mB = -1e30f, dB = 0.f;
    float4 aA = make_float4(0.f, 0.f, 0.f, 0.f);
    float4 aB = make_float4(0.f, 0.f, 0.f, 0.f);

    const int beg = g_off[d], end = g_off[d + 1];
    int idx = beg;
    for (; idx + 1 < end; idx += 2) {
        int s0 = g_csr[idx];
        int s1 = g_csr[idx + 1];
        float4 x0 = *reinterpret_cast<const float4*>(xlxr + (tbase + s0) * XLD + base);
        float4 x1 = *reinterpret_cast<const float4*>(xlxr + (tbase + s1) * XLD + base);
        float4 e0 = leaky_add(x0, xrv);
        float4 e1 = leaky_add(x1, xrv);
        float p0 = e0.x * av.x + e0.y * av.y + e0.z * av.z + e0.w * av.w;
        float p1 = e1.x * av.x + e1.y * av.y + e1.z * av.z + e1.w * av.w;
#pragma unroll
        for (int off = 16; off; off >>= 1) {
            p0 += __shfl_xor_sync(0xffffffffu, p0, off);
            p1 += __shfl_xor_sync(0xffffffffu, p1, off);
        }
        {
            float nm = fmaxf(mA, p0);
            float sc = __expf(mA - nm);
            float e  = __expf(p0 - nm);
            aA.x = aA.x * sc + e * x0.x;
            aA.y = aA.y * sc + e * x0.y;
            aA.z = aA.z * sc + e * x0.z;
            aA.w = aA.w * sc + e * x0.w;
            dA = dA * sc + e;
            mA = nm;
        }
        {
            float nm = fmaxf(mB, p1);
            float sc = __expf(mB - nm);
            float e  = __expf(p1 - nm);
            aB.x = aB.x * sc + e * x1.x;
            aB.y = aB.y * sc + e * x1.y;
            aB.z = aB.z * sc + e * x1.z;
            aB.w = aB.w * sc + e * x1.w;
            dB = dB * sc + e;
            mB = nm;
        }
    }
    if (idx < end) {
        int s0 = g_csr[idx];
        float4 x0 = *reinterpret_cast<const float4*>(xlxr + (tbase + s0) * XLD + base);
        float4 e0 = leaky_add(x0, xrv);
        float p0 = e0.x * av.x + e0.y * av.y + e0.z * av.z + e0.w * av.w;
#pragma unroll
        for (int off = 16; off; off >>= 1) p0 += __shfl_xor_sync(0xffffffffu, p0, off);
        float nm = fmaxf(mA, p0);
        float sc = __expf(mA - nm);
        float e  = __expf(p0 - nm);
        aA.x = aA.x * sc + e * x0.x;
        aA.y = aA.y * sc + e * x0.y;
        aA.z = aA.z * sc + e * x0.z;
        aA.w = aA.w * sc + e * x0.w;
        dA = dA * sc + e;
        mA = nm;
    }

    float m = fmaxf(mA, mB);
    float sA = __expf(mA - m);
    float sB = __expf(mB - m);
    float den = dA * sA + dB * sB;
    float4 acc;
    acc.x = aA.x * sA + aB.x * sB;
    acc.y = aA.y * sA + aB.y * sB;
    acc.z = aA.z * sA + aB.z * sB;
    acc.w = aA.w * sA + aB.w * sB;

    float inv = 1.f / den;
    float4 bv = *reinterpret_cast<const float4*>(bias + base);
    float4 o;
    o.x = acc.x * inv + bv.x;
    o.y = acc.y * inv + bv.y;
    o.z = acc.z * inv + bv.z;
    o.w = acc.w * inv + bv.w;
    *reinterpret_cast<float4*>(out + (tbase + d) * HCX + base) = o;
}

// ---------------- BatchNorm ----------------
#define BN_ROWS 200
__global__ void bn_stats_kernel(const float* __restrict__ x) {
    int c = threadIdx.x;
    int t = blockIdx.y;
    const float* xt = x + (size_t)t * NN * HCX;
    int rb = blockIdx.x * BN_ROWS;
    int re = rb + BN_ROWS; if (re > NN) re = NN;
    float s0 = 0.f, s1 = 0.f, q0 = 0.f, q1 = 0.f;
    for (int r = rb; r < re; r++) {
        float v0 = xt[(size_t)r * HCX + c];
        float v1 = xt[(size_t)r * HCX + c + 256];
        s0 += v0; q0 += v0 * v0;
        s1 += v1; q1 += v1 * v1;
    }
    atomicAdd(&g_sum[t * HCX + c], s0);
    atomicAdd(&g_sum[t * HCX + c + 256], s1);
    atomicAdd(&g_sumsq[t * HCX + c], q0);
    atomicAdd(&g_sumsq[t * HCX + c + 256], q1);
}

__global__ void bn_finalize_kernel(const float* __restrict__ gamma, const float* __restrict__ beta) {
    int c = threadIdx.x;
    int t = blockIdx.x;
    int i = t * HCX + c;
    float mean = g_sum[i] * (1.f / NN);
    float var  = g_sumsq[i] * (1.f / NN) - mean * mean;
    float a = gamma[c] * rsqrtf(var + 1e-5f);
    g_scale[i] = a;
    g_shift[i] = beta[c] - mean * a;
    g_sum[i] = 0.f;
    g_sumsq[i] = 0.f;
}

__global__ void bn_apply_kernel(const float* __restrict__ x, float* __restrict__ y) {
    int i = blockIdx.x * blockDim.x + threadIdx.x;
    if (i >= TNN * HCX / 4) return;
    int r  = i >> 7;
    int t  = r / NN;
    int c4 = (i & 127) * 4;
    const float* sc = g_scale + t * HCX + c4;
    const float* sh = g_shift + t * HCX + c4;
    float4 v = reinterpret_cast<const float4*>(x)[i];
    float4 o;
    o.x = f2tff(fmaxf(0.f, v.x * sc[0] + sh[0]));
    o.y = f2tff(fmaxf(0.f, v.y * sc[1] + sh[1]));
    o.z = f2tff(fmaxf(0.f, v.z * sc[2] + sh[2]));
    o.w = f2tff(fmaxf(0.f, v.w * sc[3] + sh[3]));
    reinterpret_cast<float4*>(y)[i] = o;
}

// ---------------- host side ----------------
static inline void launch_gemm(int M, int Ncols, int K,
                               const float* A, int lda, const float* B, int ldb,
                               const float* bias, const float* addmat, int addld,
                               float* C, int ldc, int oproj)
{
    if (Ncols == 64) {
        dim3 grid((M + GBM - 1) / GBM, 1);
        gemm_tc_kernel<64, 0><<<grid, 256>>>(M, Ncols, K, A, lda, B, ldb, bias,
                                             addmat, addld, C, ldc, oproj, 0);
    } else {
        dim3 grid((M + GBM - 1) / GBM, (Ncols + 127) / 128);
        gemm_tc_kernel<128, 0><<<grid, 256>>>(M, Ncols, K, A, lda, B, ldb, bias,
                                              addmat, addld, C, ldc, oproj, 0);
    }
}

extern "C" void kernel_launch(void* const* d_in, const int* in_sizes, int n_in,
                              void* d_out, int out_size)
{
    const float* x_static = (const float*)d_in[0];
    const float* dyn      = (const float*)d_in[1];
    const int*   ei       = (const int*)  d_in[2];
    const float* W_ih     = (const float*)d_in[3];
    const float* W_hh     = (const float*)d_in[4];
    const float* b_ih     = (const float*)d_in[5];
    const float* b_hh     = (const float*)d_in[6];
    const float* Wl1      = (const float*)d_in[7];
    const float* Wr1      = (const float*)d_in[8];
    const float* att1     = (const float*)d_in[9];
    const float* bg1      = (const float*)d_in[10];
    const float* Wl2      = (const float*)d_in[11];
    const float* Wr2      = (const float*)d_in[12];
    const float* att2     = (const float*)d_in[13];
    const float* bg2      = (const float*)d_in[14];
    const float* gamma1   = (const float*)d_in[15];
    const float* beta1    = (const float*)d_in[16];
    const float* gamma2   = (const float*)d_in[17];
    const float* beta2    = (const float*)d_in[18];
    const float* Wp       = (const float*)d_in[19];
    const float* bp       = (const float*)d_in[20];
    float* out = (float*)d_out;

    void* p;
    cudaGetSymbolAddress(&p, g_hs);     float* hs    = (float*)p;
    cudaGetSymbolAddress(&p, g_AB);     float* AB    = (float*)p;
    cudaGetSymbolAddress(&p, g_bufC);   float* bC    = (float*)p;
    cudaGetSymbolAddress(&p, g_bufD);   float* bD    = (float*)p;
    cudaGetSymbolAddress(&p, g_xscat);  float* xsc   = (float*)p;
    cudaGetSymbolAddress(&p, g_gatesx); float* gx    = (float*)p;
    cudaGetSymbolAddress(&p, g_dynt);   float* dynt  = (float*)p;
    cudaGetSymbolAddress(&p, g_xst);    float* xst   = (float*)p;
    cudaGetSymbolAddress(&p, g_WcatS);  float* WcS   = (float*)p;
    cudaGetSymbolAddress(&p, g_WcatD);  float* WcD   = (float*)p;
    cudaGetSymbolAddress(&p, g_Wcat2);  float* Wc2   = (float*)p;
    cudaGetSymbolAddress(&p, g_Wih);    float* Wih   = (float*)p;
    cudaGetSymbolAddress(&p, g_Whh);    float* Whh   = (float*)p;
    cudaGetSymbolAddress(&p, g_Wpt);    float* Wpt   = (float*)p;
    cudaGetSymbolAddress(&p, g_bsum);   float* bsum  = (float*)p;

    // (1) fused setup: bsum + tf32 weight packs (LSTM gate-interleaved) + inits
    setup_kernel<<<(XLD * HCX + 255) / 256, 256>>>(b_ih, b_hh, Wl1, Wr1, Wl2, Wr2,
                                                   W_ih, W_hh, Wp);
    // (2) tf32 input conversions
    cvt_inputs_kernel<<<(TNN * DDIM + 255) / 256, 256>>>(dyn, x_static);

    // (3) LSTM input-side gates for all (n,t): packed layout
    launch_gemm(TNN, 4 * HLX, DDIM, dynt, DDIM, Wih, DDIM,
                bsum, 0, 0, gx, 4 * HLX, 0);

    // (4) t=0 gate pass, then 7 recurrence GEMMs with FUSED gate epilogue
    lstm_gate0_kernel<<<(NN * HLX + 255) / 256, 256>>>();
    for (int t = 1; t < TT; t++) {
        dim3 grid((NN + GBM - 1) / GBM, 4);
        gemm_tc_kernel<128, 1><<<grid, 256>>>(NN, 4 * HLX, HLX,
            hs + (size_t)(t - 1) * NN * HLX, HLX, Whh, HLX,
            0, 0, 0, 0, 0, 0, t);
    }

    // --- CSR build
    count_kernel<<<(EE + 255) / 256, 256>>>(ei);
    scan_kernel<<<1, 1024>>>();
    fill_kernel<<<(ETOT + 255) / 256, 256>>>(ei);

    // --- static projection (combined xl|xr, constant across t)
    launch_gemm(NN, XLD, DSX, xst, DSX, WcS, DSX,
                0, 0, 0, xsc, XLD, 0);

    // --- layer 1 (batched): AB = hs @ WcD^T + xsc[r%NN]
    launch_gemm(TNN, XLD, HLX, hs, HLX, WcD, HLX,
                0, xsc, XLD, AB, XLD, 0);
    gat_kernel<<<dim3(NN, TT), 128>>>(AB, att1, bg1, bC);

    bn_stats_kernel<<<dim3((NN + BN_ROWS - 1) / BN_ROWS, TT), 256>>>(bC);
    bn_finalize_kernel<<<TT, 512>>>(gamma1, beta1);
    bn_apply_kernel<<<(TNN * HCX / 4 + 255) / 256, 256>>>(bC, bD);

    // --- layer 2 (batched)
    launch_gemm(TNN, XLD, HCX, bD, HCX, Wc2, HCX,
                0, 0, 0, AB, XLD, 0);
    gat_kernel<<<dim3(NN, TT), 128>>>(AB, att2, bg2, bC);

    bn_stats_kernel<<<dim3((NN + BN_ROWS - 1) / BN_ROWS, TT), 256>>>(bC);
    bn_finalize_kernel<<<TT, 512>>>(gamma2, beta2);

    // --- projection: BN2+relu fused into A-fetch, output remapped [N,T,EMB]
    gemm_proj_kernel<<<(TNN + GBM - 1) / GBM, 256>>>(TNN, EMBX, HCX,
                                                     bC, HCX, Wpt, HCX, bp, out);
}

// round 16
// speedup vs baseline: 1.2158x; 1.2158x over previous
#include <cuda_runtime.h>
#include <cuda_fp16.h>
#include <math.h>
#include <stdint.h>

// ---------------- problem constants (fixed shapes) ----------------
#define NN    20000
#define TT    8
#define DSX   16
#define DDIM  8
#define EE    320000
#define HLX   128
#define GHX   4
#define GCX   128
#define HCX   512
#define EMBX  64
#define IN1X  (DSX + HLX)       // 144
#define ETOT  (EE + NN)
#define TNN   (TT * NN)         // 160000
#define XLD   (2 * HCX)         // 1024 combined xl|xr row stride

// ---------------- scratch ----------------
__device__ float  g_hs[TT * NN * HLX];        // tf32-rounded h (recurrence GEMM)
__device__ __half g_hsh[TT * NN * HLX];       // fp16 h (layer-1 GEMM A)
__device__ float  g_c[NN * HLX];
__device__ float  g_gate[NN * 4 * HLX];
__device__ float  g_gatesx[TNN * 4 * HLX];
__device__ float  g_AB[(size_t)TNN * XLD];
__device__ float  g_bufC[TNN * HCX];
__device__ __half g_bufDh[TNN * HCX];         // BN+relu output fp16 (layer-2 A)
__device__ float  g_xscat[NN * XLD];
__device__ float  g_dynt[TNN * DDIM];
__device__ float  g_xst[NN * DSX];
__device__ float  g_WcatS[XLD * DSX];
__device__ __half g_WcDh[XLD * HLX];          // fp16 layer-1 dyn weights
__device__ __half g_Wc2h[XLD * HCX];          // fp16 layer-2 weights
__device__ float  g_Wih[4 * HLX * DDIM];
__device__ float  g_Whh[4 * HLX * HLX];
__device__ float  g_Wpt[EMBX * HCX];
__device__ float  g_bsum[4 * HLX];
__device__ float  g_sum[TT * HCX];
__device__ float  g_sumsq[TT * HCX];
__device__ float  g_scale[TT * HCX];
__device__ float  g_shift[TT * HCX];
__device__ int    g_deg[NN];
__device__ int    g_off[NN + 1];
__device__ int    g_cursor[NN];
__device__ int    g_csr[ETOT];

__device__ __forceinline__ uint32_t f2tf(float f) {
    uint32_t u;
    asm("cvt.rna.tf32.f32 %0, %1;" : "=r"(u) : "f"(f));
    return u;
}
__device__ __forceinline__ float f2tff(float f) { return __uint_as_float(f2tf(f)); }

// ---------------- fused setup ----------------
__global__ void setup_kernel(const float* __restrict__ b_ih, const float* __restrict__ b_hh,
                             const float* __restrict__ Wl1, const float* __restrict__ Wr1,
                             const float* __restrict__ Wl2, const float* __restrict__ Wr2,
                             const float* __restrict__ W_ih, const float* __restrict__ W_hh,
                             const float* __restrict__ Wp)
{
    int i = blockIdx.x * blockDim.x + threadIdx.x;
    if (i < 4 * HLX) g_bsum[i] = b_ih[i] + b_hh[i];
    if (i < NN) g_deg[i] = 1;           // self loop
    if (i < TT * HCX) { g_sum[i] = 0.f; g_sumsq[i] = 0.f; }
    if (i < 4 * HLX * DDIM)  g_Wih[i] = f2tff(W_ih[i]);
    if (i < 4 * HLX * HLX)   g_Whh[i] = f2tff(W_hh[i]);
    if (i < EMBX * HCX)      g_Wpt[i] = f2tff(Wp[i]);
    if (i < XLD * IN1X) {
        int j = i / IN1X, k = i % IN1X;
        const float* W = (j < HCX) ? Wl1 : Wr1;
        int jj = j & (HCX - 1);
        float v = W[(size_t)jj * IN1X + k];
        if (k < DSX) g_WcatS[j * DSX + k] = f2tff(v);
        else         g_WcDh[j * HLX + (k - DSX)] = __float2half_rn(v);
    }
    if (i < XLD * HCX) {
        int j = i / HCX, k = i % HCX;
        float v = (j < HCX) ? Wl2[(size_t)j * HCX + k] : Wr2[(size_t)(j - HCX) * HCX + k];
        g_Wc2h[i] = __float2half_rn(v);
    }
}

__global__ void cvt_inputs_kernel(const float* __restrict__ dyn, const float* __restrict__ xs) {
    int i = blockIdx.x * blockDim.x + threadIdx.x;
    if (i < TNN * DDIM) g_dynt[i] = f2tff(dyn[i]);
    if (i < NN * DSX)   g_xst[i]  = f2tff(xs[i]);
}

__global__ void count_kernel(const int* __restrict__ ei) {
    int i = blockIdx.x * blockDim.x + threadIdx.x;
    if (i < EE) atomicAdd(&g_deg[ei[EE + i]], 1);
}

__global__ void scan_kernel() {
    __shared__ int s[1024];
    const int t = threadIdx.x;
    const int CH = (NN + 1023) / 1024;
    int beg = t * CH;
    int end = beg + CH; if (end > NN) end = NN;
    int sum = 0;
    for (int i = beg; i < end; i++) sum += g_deg[i];
    int v = sum;
    s[t] = v;
    __syncthreads();
    for (int off = 1; off < 1024; off <<= 1) {
        int add = (t >= off) ? s[t - off] : 0;
        __syncthreads();
        v += add;
        s[t] = v;
        __syncthreads();
    }
    int run = (t == 0) ? 0 : s[t - 1];
    for (int i = beg; i < end; i++) { g_off[i] = run; g_cursor[i] = run; run += g_deg[i]; }
    if (t == 1023) g_off[NN] = s[1023];
}

__global__ void fill_kernel(const int* __restrict__ ei) {
    int i = blockIdx.x * blockDim.x + threadIdx.x;
    if (i < EE) {
        int s = ei[i];
        int d = ei[EE + i];
        int pos = atomicAdd(&g_cursor[d], 1);
        g_csr[pos] = s;
    } else if (i < ETOT) {
        int d = i - EE;
        int pos = atomicAdd(&g_cursor[d], 1);
        g_csr[pos] = d;
    }
}

// ---------------- common helpers ----------------
__device__ __forceinline__ void cp16(uint32_t saddr, const void* g, bool pred) {
    int bytes = pred ? 16 : 0;
    asm volatile("cp.async.cg.shared.global [%0], [%1], 16, %2;\n"
                 :: "r"(saddr), "l"(g), "r"(bytes));
}

__device__ __forceinline__ void mma_tf32(float c[4], uint32_t a0, uint32_t a1,
                                         uint32_t a2, uint32_t a3,
                                         uint32_t b0, uint32_t b1)
{
    asm volatile(
        "mma.sync.aligned.m16n8k8.row.col.f32.tf32.tf32.f32 "
        "{%0,%1,%2,%3}, {%4,%5,%6,%7}, {%8,%9}, {%0,%1,%2,%3};\n"
        : "+f"(c[0]), "+f"(c[1]), "+f"(c[2]), "+f"(c[3])
        : "r"(a0), "r"(a1), "r"(a2), "r"(a3), "r"(b0), "r"(b1));
}

__device__ __forceinline__ void mma_f16(float c[4], uint32_t a0, uint32_t a1,
                                        uint32_t a2, uint32_t a3,
                                        uint32_t b0, uint32_t b1)
{
    asm volatile(
        "mma.sync.aligned.m16n8k16.row.col.f32.f16.f16.f32 "
        "{%0,%1,%2,%3}, {%4,%5,%6,%7}, {%8,%9}, {%0,%1,%2,%3};\n"
        : "+f"(c[0]), "+f"(c[1]), "+f"(c[2]), "+f"(c[3])
        : "r"(a0), "r"(a1), "r"(a2), "r"(a3), "r"(b0), "r"(b1));
}

// ---------------- tf32 GEMM (cp.async, 2-stage) — small GEMMs -------------
#define GBM 128
#define GBK 16
#define SKP 20

template<int TBN>
__global__ __launch_bounds__(256)
void gemm_tc_kernel(int M, int Ncols, int K,
                    const float* __restrict__ A, int lda,
                    const float* __restrict__ B, int ldb,
                    const float* __restrict__ bias,
                    const float* __restrict__ addmat, int addld,
                    float* __restrict__ C, int ldc, int oproj)
{
    constexpr int WROW = (TBN == 128) ? 2 : 4;
    constexpr int MT   = (GBM / WROW) / 16;

    __shared__ float As[2][GBM][SKP];
    __shared__ float Bs[2][TBN][SKP];

    const int ktiles = (K + GBK - 1) / GBK;
    const int tid = threadIdx.x;
    const int brow = blockIdx.x * GBM;
    const int bcol = blockIdx.y * TBN;
    const int lane = tid & 31;
    const int warp = tid >> 5;
    const int g    = lane >> 2;
    const int tig  = lane & 3;
    const int wm   = warp % WROW;
    const int wn   = warp / WROW;

    const int arow = tid >> 2;
    const int kq   = (tid & 3) * 4;

    uint32_t sA0 = (uint32_t)__cvta_generic_to_shared(&As[0][arow][kq]);
    uint32_t sA1 = (uint32_t)__cvta_generic_to_shared(&As[0][arow + 64][kq]);
    uint32_t sB0 = (uint32_t)__cvta_generic_to_shared(&Bs[0][arow][kq]);
    uint32_t sB1 = (TBN == 128) ? (uint32_t)__cvta_generic_to_shared(&Bs[0][arow + 64][kq]) : 0u;
    const uint32_t aStride = (uint32_t)(GBM * SKP * 4);
    const uint32_t bStride = (uint32_t)(TBN * SKP * 4);

    float acc[MT][4][4];
#pragma unroll
    for (int mt = 0; mt < MT; mt++)
#pragma unroll
        for (int nt = 0; nt < 4; nt++)
#pragma unroll
            for (int i = 0; i < 4; i++) acc[mt][nt][i] = 0.f;

    auto issue = [&](int kt) {
        const int buf = kt & 1;
        const int k0 = kt * GBK + kq;
        const bool kok = k0 < K;
        const int kc = kok ? k0 : 0;
        {
            int r = brow + arow;
            bool p = (r < M) && kok;
            cp16(sA0 + buf * aStride, A + (size_t)(p ? r : 0) * lda + kc, p);
        }
        {
            int r = brow + arow + 64;
            bool p = (r < M) && kok;
            cp16(sA1 + buf * aStride, A + (size_t)(p ? r : 0) * lda + kc, p);
        }
        {
            int c = bcol + arow;
            bool p = (c < Ncols) && kok;
            cp16(sB0 + buf * bStride, B + (size_t)(p ? c : 0) * ldb + kc, p);
        }
        if (TBN == 128) {
            int c = bcol + arow + 64;
            bool p = (c < Ncols) && kok;
            cp16(sB1 + buf * bStride, B + (size_t)(p ? c : 0) * ldb + kc, p);
        }
        asm volatile("cp.async.commit_group;\n" ::: "memory");
    };

    issue(0);
    if (ktiles > 1) issue(1);

    for (int kt = 0; kt < ktiles; kt++) {
        if (kt + 1 < ktiles) asm volatile("cp.async.wait_group 1;\n" ::: "memory");
        else                 asm volatile("cp.async.wait_group 0;\n" ::: "memory");
        __syncthreads();

        const int buf = kt & 1;
#pragma unroll
        for (int ks = 0; ks < 2; ks++) {
            const int kb = ks * 8;
            uint32_t af[MT][4], bf[4][2];
#pragma unroll
            for (int mt = 0; mt < MT; mt++) {
                int r0 = wm * (GBM / WROW) + mt * 16 + g;
                af[mt][0] = __float_as_uint(As[buf][r0    ][kb + tig]);
                af[mt][1] = __float_as_uint(As[buf][r0 + 8][kb + tig]);
                af[mt][2] = __float_as_uint(As[buf][r0    ][kb + tig + 4]);
                af[mt][3] = __float_as_uint(As[buf][r0 + 8][kb + tig + 4]);
            }
#pragma unroll
            for (int nt = 0; nt < 4; nt++) {
                int cb = wn * 32 + nt * 8 + g;
                bf[nt][0] = __float_as_uint(Bs[buf][cb][kb + tig]);
                bf[nt][1] = __float_as_uint(Bs[buf][cb][kb + tig + 4]);
            }
#pragma unroll
            for (int mt = 0; mt < MT; mt++)
#pragma unroll
                for (int nt = 0; nt < 4; nt++)
                    mma_tf32(acc[mt][nt], af[mt][0], af[mt][1], af[mt][2], af[mt][3],
                             bf[nt][0], bf[nt][1]);
        }
        __syncthreads();
        if (kt + 2 < ktiles) issue(kt + 2);
    }

#pragma unroll
    for (int mt = 0; mt < MT; mt++) {
        int gr0 = brow + wm * (GBM / WROW) + mt * 16 + g;
        int gr1 = gr0 + 8;
#pragma unroll
        for (int nt = 0; nt < 4; nt++) {
            int gc = bcol + wn * 32 + nt * 8 + 2 * tig;
            if (gc >= Ncols) continue;
            float bx = bias ? bias[gc]     : 0.f;
            float by = bias ? bias[gc + 1] : 0.f;
            if (gr0 < M) {
                float ax = bx, ay = by;
                if (addmat) {
                    const float* ad = addmat + (size_t)(gr0 % NN) * addld + gc;
                    ax += ad[0]; ay += ad[1];
                }
                float2 v = make_float2(acc[mt][nt][0] + ax, acc[mt][nt][1] + ay);
                size_t off = oproj ? ((size_t)(gr0 % NN) * (TT * EMBX) + (gr0 / NN) * EMBX + gc)
                                   : ((size_t)gr0 * ldc + gc);
                *reinterpret_cast<float2*>(C + off) = v;
            }
            if (gr1 < M) {
                float ax = bx, ay = by;
                if (addmat) {
                    const float* ad = addmat + (size_t)(gr1 % NN) * addld + gc;
                    ax += ad[0]; ay += ad[1];
                }
                float2 v = make_float2(acc[mt][nt][2] + ax, acc[mt][nt][3] + ay);
                size_t off = oproj ? ((size_t)(gr1 % NN) * (TT * EMBX) + (gr1 / NN) * EMBX + gc)
                                   : ((size_t)gr1 * ldc + gc);
                *reinterpret_cast<float2*>(C + off) = v;
            }
        }
    }
}

// ---------------- fp16 GEMM (m16n8k16) — layer-1/layer-2 -------------------
// Requires M%128==0, Ncols%128==0, K%16==0 (exact at both call sites).
// smem pitch 40 halfs (20 words) -> all fragment LDS.32 bank-conflict-free.
#define HSKP 40

__global__ __launch_bounds__(256)
void gemm_h_kernel(int M, int Ncols, int K,
                   const __half* __restrict__ A, int lda,
                   const __half* __restrict__ B, int ldb,
                   const float* __restrict__ addmat, int addld,
                   float* __restrict__ C, int ldc)
{
    __shared__ __half As[2][GBM][HSKP];
    __shared__ __half Bs[2][GBM][HSKP];

    const int ktiles = K / 16;
    const int tid = threadIdx.x;
    const int brow = blockIdx.x * GBM;
    const int bcol = blockIdx.y * GBM;
    const int lane = tid & 31;
    const int warp = tid >> 5;
    const int g    = lane >> 2;
    const int tig  = lane & 3;
    const int wm   = warp & 1;     // 2 warp rows -> 64-row tiles
    const int wn   = warp >> 1;    // 4 warp cols -> 32-col tiles

    const int arow = tid >> 1;        // 0..127
    const int kh   = (tid & 1) * 8;   // 0 or 8 (halfs)

    uint32_t sA = (uint32_t)__cvta_generic_to_shared(&As[0][arow][kh]);
    uint32_t sB = (uint32_t)__cvta_generic_to_shared(&Bs[0][arow][kh]);
    const uint32_t stride = (uint32_t)(GBM * HSKP * 2);

    float acc[4][4][4];
#pragma unroll
    for (int mt = 0; mt < 4; mt++)
#pragma unroll
        for (int nt = 0; nt < 4; nt++)
#pragma unroll
            for (int i = 0; i < 4; i++) acc[mt][nt][i] = 0.f;

    auto issue = [&](int kt) {
        const int buf = kt & 1;
        const int kc = kt * 16 + kh;
        cp16(sA + buf * stride, A + (size_t)(brow + arow) * lda + kc, true);
        cp16(sB + buf * stride, B + (size_t)(bcol + arow) * ldb + kc, true);
        asm volatile("cp.async.commit_group;\n" ::: "memory");
    };

    issue(0);
    if (ktiles > 1) issue(1);

    for (int kt = 0; kt < ktiles; kt++) {
        if (kt + 1 < ktiles) asm volatile("cp.async.wait_group 1;\n" ::: "memory");
        else                 asm volatile("cp.async.wait_group 0;\n" ::: "memory");
        __syncthreads();

        const int buf = kt & 1;
        uint32_t af[4][4], bf[4][2];
#pragma unroll
        for (int mt = 0; mt < 4; mt++) {
            int r0 = wm * 64 + mt * 16 + g;
            af[mt][0] = *reinterpret_cast<const uint32_t*>(&As[buf][r0    ][2 * tig]);
            af[mt][1] = *reinterpret_cast<const uint32_t*>(&As[buf][r0 + 8][2 * tig]);
            af[mt][2] = *reinterpret_cast<const uint32_t*>(&As[buf][r0    ][2 * tig + 8]);
            af[mt][3] = *reinterpret_cast<const uint32_t*>(&As[buf][r0 + 8][2 * tig + 8]);
        }
#pragma unroll
        for (int nt = 0; nt < 4; nt++) {
            int cb = wn * 32 + nt * 8 + g;
            bf[nt][0] = *reinterpret_cast<const uint32_t*>(&Bs[buf][cb][2 * tig]);
            bf[nt][1] = *reinterpret_cast<const uint32_t*>(&Bs[buf][cb][2 * tig + 8]);
        }
#pragma unroll
        for (int mt = 0; mt < 4; mt++)
#pragma unroll
            for (int nt = 0; nt < 4; nt++)
                mma_f16(acc[mt][nt], af[mt][0], af[mt][1], af[mt][2], af[mt][3],
                        bf[nt][0], bf[nt][1]);
        __syncthreads();
        if (kt + 2 < ktiles) issue(kt + 2);
    }

#pragma unroll
    for (int mt = 0; mt < 4; mt++) {
        int gr0 = brow + wm * 64 + mt * 16 + g;
        int gr1 = gr0 + 8;
#pragma unroll
        for (int nt = 0; nt < 4; nt++) {
            int gc = bcol + wn * 32 + nt * 8 + 2 * tig;
            float ax = 0.f, ay = 0.f, ax1 = 0.f, ay1 = 0.f;
            if (addmat) {
                const float* ad0 = addmat + (size_t)(gr0 % NN) * addld + gc;
                const float* ad1 = addmat + (size_t)(gr1 % NN) * addld + gc;
                ax  = ad0[0]; ay  = ad0[1];
                ax1 = ad1[0]; ay1 = ad1[1];
            }
            *reinterpret_cast<float2*>(C + (size_t)gr0 * ldc + gc) =
                make_float2(acc[mt][nt][0] + ax, acc[mt][nt][1] + ay);
            *reinterpret_cast<float2*>(C + (size_t)gr1 * ldc + gc) =
                make_float2(acc[mt][nt][2] + ax1, acc[mt][nt][3] + ay1);
        }
    }
}

// ---------------- LSTM gate nonlinearity ----------------
__device__ __forceinline__ float sigm(float x) { return 1.f / (1.f + __expf(-x)); }

__global__ void lstm_gate_kernel(const float* __restrict__ G, int t, int hzero) {
    int i = blockIdx.x * blockDim.x + threadIdx.x;
    if (i >= NN * HLX) return;
    int n = i / HLX, j = i % HLX;
    const float* gx = g_gatesx + ((size_t)n * TT + t) * (4 * HLX);
    float vi = gx[j], vf = gx[HLX + j], vg = gx[2 * HLX + j], vo = gx[3 * HLX + j];
    if (!hzero) {
        const float* g = G + (size_t)n * (4 * HLX);
        vi += g[j]; vf += g[HLX + j]; vg += g[2 * HLX + j]; vo += g[3 * HLX + j];
    }
    float gi = sigm(vi);
    float gf = sigm(vf);
    float gg = tanhf(vg);
    float go = sigm(vo);
    float cold = hzero ? 0.f : g_c[i];
    float c = gf * cold + gi * gg;
    g_c[i] = c;
    float h = go * tanhf(c);
    size_t idx = (size_t)t * NN * HLX + i;
    g_hs[idx]  = f2tff(h);
    g_hsh[idx] = __float2half_rn(h);
}

// ---------------- GATv2 aggregation (batched over t, 2-way ILP) ----------
__device__ __forceinline__ float4 leaky_add(float4 a, const float4& b) {
    float4 e;
    e.x = a.x + b.x; e.x = e.x > 0.f ? e.x : 0.2f * e.x;
    e.y = a.y + b.y; e.y = e.y > 0.f ? e.y : 0.2f * e.y;
    e.z = a.z + b.z; e.z = e.z > 0.f ? e.z : 0.2f * e.z;
    e.w = a.w + b.w; e.w = e.w > 0.f ? e.w : 0.2f * e.w;
    return e;
}

__global__ void gat_kernel(const float* __restrict__ xlxr,
                           const float* __restrict__ att,
                           const float* __restrict__ bias,
                           float* __restrict__ out)
{
    const int d = blockIdx.x;
    const int t = blockIdx.y;
    const int w = threadIdx.x >> 5;
    const int lane = threadIdx.x & 31;
    const int base = w * GCX + lane * 4;
    const size_t tbase = (size_t)t * NN;

    const float4 xrv = *reinterpret_cast<const float4*>(xlxr + (tbase + d) * XLD + HCX + base);
    const float4 av  = *reinterpret_cast<const float4*>(att + w * GCX + lane * 4);

    float mA = -1e30f, dA = 0.f, mB = -1e30f, dB = 0.f;
    float4 aA = make_float4(0.f, 0.f, 0.f, 0.f);
    float4 aB = make_float4(0.f, 0.f, 0.f, 0.f);

    const int beg = g_off[d], end = g_off[d + 1];
    int idx = beg;
    for (; idx + 1 < end; idx += 2) {
        int s0 = g_csr[idx];
        int s1 = g_csr[idx + 1];
        float4 x0 = *reinterpret_cast<const float4*>(xlxr + (tbase + s0) * XLD + base);
        float4 x1 = *reinterpret_cast<const float4*>(xlxr + (tbase + s1) * XLD + base);
        float4 e0 = leaky_add(x0, xrv);
        float4 e1 = leaky_add(x1, xrv);
        float p0 = e0.x * av.x + e0.y * av.y + e0.z * av.z + e0.w * av.w;
        float p1 = e1.x * av.x + e1.y * av.y + e1.z * av.z + e1.w * av.w;
#pragma unroll
        for (int off = 16; off; off >>= 1) {
            p0 += __shfl_xor_sync(0xffffffffu, p0, off);
            p1 += __shfl_xor_sync(0xffffffffu, p1, off);
        }
        {
            float nm = fmaxf(mA, p0);
            float sc = __expf(mA - nm);
            float e  = __expf(p0 - nm);
            aA.x = aA.x * sc + e * x0.x;
            aA.y = aA.y * sc + e * x0.y;
            aA.z = aA.z * sc + e * x0.z;
            aA.w = aA.w * sc + e * x0.w;
            dA = dA * sc + e;
            mA = nm;
        }
        {
            float nm = fmaxf(mB, p1);
            float sc = __expf(mB - nm);
            float e  = __expf(p1 - nm);
            aB.x = aB.x * sc + e * x1.x;
            aB.y = aB.y * sc + e * x1.y;
            aB.z = aB.z * sc + e * x1.z;
            aB.w = aB.w * sc + e * x1.w;
            dB = dB * sc + e;
            mB = nm;
        }
    }
    if (idx < end) {
        int s0 = g_csr[idx];
        float4 x0 = *reinterpret_cast<const float4*>(xlxr + (tbase + s0) * XLD + base);
        float4 e0 = leaky_add(x0, xrv);
        float p0 = e0.x * av.x + e0.y * av.y + e0.z * av.z + e0.w * av.w;
#pragma unroll
        for (int off = 16; off; off >>= 1) p0 += __shfl_xor_sync(0xffffffffu, p0, off);
        float nm = fmaxf(mA, p0);
        float sc = __expf(mA - nm);
        float e  = __expf(p0 - nm);
        aA.x = aA.x * sc + e * x0.x;
        aA.y = aA.y * sc + e * x0.y;
        aA.z = aA.z * sc + e * x0.z;
        aA.w = aA.w * sc + e * x0.w;
        dA = dA * sc + e;
        mA = nm;
    }

    float m = fmaxf(mA, mB);
    float sA = __expf(mA - m);
    float sB = __expf(mB - m);
    float den = dA * sA + dB * sB;
    float4 acc;
    acc.x = aA.x * sA + aB.x * sB;
    acc.y = aA.y * sA + aB.y * sB;
    acc.z = aA.z * sA + aB.z * sB;
    acc.w = aA.w * sA + aB.w * sB;

    float inv = 1.f / den;
    float4 bv = *reinterpret_cast<const float4*>(bias + base);
    float4 o;
    o.x = acc.x * inv + bv.x;
    o.y = acc.y * inv + bv.y;
    o.z = acc.z * inv + bv.z;
    o.w = acc.w * inv + bv.w;
    *reinterpret_cast<float4*>(out + (tbase + d) * HCX + base) = o;
}

// ---------------- BatchNorm ----------------
#define BN_ROWS 200
__global__ void bn_stats_kernel(const float* __restrict__ x) {
    int c = threadIdx.x;
    int t = blockIdx.y;
    const float* xt = x + (size_t)t * NN * HCX;
    int rb = blockIdx.x * BN_ROWS;
    int re = rb + BN_ROWS; if (re > NN) re = NN;
    float s0 = 0.f, s1 = 0.f, q0 = 0.f, q1 = 0.f;
    for (int r = rb; r < re; r++) {
        float v0 = xt[(size_t)r * HCX + c];
        float v1 = xt[(size_t)r * HCX + c + 256];
        s0 += v0; q0 += v0 * v0;
        s1 += v1; q1 += v1 * v1;
    }
    atomicAdd(&g_sum[t * HCX + c], s0);
    atomicAdd(&g_sum[t * HCX + c + 256], s1);
    atomicAdd(&g_sumsq[t * HCX + c], q0);
    atomicAdd(&g_sumsq[t * HCX + c + 256], q1);
}

__global__ void bn_finalize_kernel(const float* __restrict__ gamma, const float* __restrict__ beta) {
    int c = threadIdx.x;
    int t = blockIdx.x;
    int i = t * HCX + c;
    float mean = g_sum[i] * (1.f / NN);
    float var  = g_sumsq[i] * (1.f / NN) - mean * mean;
    float a = gamma[c] * rsqrtf(var + 1e-5f);
    g_scale[i] = a;
    g_shift[i] = beta[c] - mean * a;
    g_sum[i] = 0.f;
    g_sumsq[i] = 0.f;
}

// BN apply + relu -> fp16 (feeds layer-2 fp16 GEMM)
__global__ void bn_apply_kernel(const float* __restrict__ x, __half* __restrict__ y) {
    int i = blockIdx.x * blockDim.x + threadIdx.x;
    if (i >= TNN * HCX / 4) return;
    int r  = i >> 7;
    int t  = r / NN;
    int c4 = (i & 127) * 4;
    const float* sc = g_scale + t * HCX + c4;
    const float* sh = g_shift + t * HCX + c4;
    float4 v = reinterpret_cast<const float4*>(x)[i];
    float ox = fmaxf(0.f, v.x * sc[0] + sh[0]);
    float oy = fmaxf(0.f, v.y * sc[1] + sh[1]);
    float oz = fmaxf(0.f, v.z * sc[2] + sh[2]);
    float ow = fmaxf(0.f, v.w * sc[3] + sh[3]);
    __half2* y2 = reinterpret_cast<__half2*>(y);
    y2[i * 2]     = __floats2half2_rn(ox, oy);
    y2[i * 2 + 1] = __floats2half2_rn(oz, ow);
}

// ---------------- projection GEMM: register-staged, BN+relu fused on A ----
__global__ __launch_bounds__(256)
void gemm_proj_kernel(int M, int Ncols, int K,
                      const float* __restrict__ A, int lda,
                      const float* __restrict__ B, int ldb,
                      const float* __restrict__ bias,
                      float* __restrict__ C)
{
    constexpr int TBN = 64, WROW = 4, MT = 2;
    __shared__ uint32_t As[2][GBM][SKP];
    __shared__ uint32_t Bs[2][TBN][SKP];

    const int ktiles = K / GBK;
    const int tid = threadIdx.x;
    const int brow = blockIdx.x * GBM;
    const int bcol = 0;
    const int lane = tid & 31;
    const int warp = tid >> 5;
    const int g    = lane >> 2;
    const int tig  = lane & 3;
    const int wm   = warp % WROW;
    const int wn   = warp / WROW;

    const int arow = tid >> 2;
    const int kq   = (tid & 3) * 4;

    float acc[MT][4][4];
#pragma unroll
    for (int mt = 0; mt < MT; mt++)
#pragma unroll
        for (int nt = 0; nt < 4; nt++)
#pragma unroll
            for (int i = 0; i < 4; i++) acc[mt][nt][i] = 0.f;

    auto fetchA = [&](int r, int gk) -> float4 {
        float4 z = make_float4(0.f, 0.f, 0.f, 0.f);
        if (r >= M) return z;
        float4 v = *reinterpret_cast<const float4*>(A + (size_t)r * lda + gk);
        int t = r / NN;
        const float* sc = g_scale + t * HCX + gk;
        const float* sh = g_shift + t * HCX + gk;
        v.x = f2tff(fmaxf(0.f, v.x * sc[0] + sh[0]));
        v.y = f2tff(fmaxf(0.f, v.y * sc[1] + sh[1]));
        v.z = f2tff(fmaxf(0.f, v.z * sc[2] + sh[2]));
        v.w = f2tff(fmaxf(0.f, v.w * sc[3] + sh[3]));
        return v;
    };
    auto fetchB = [&](int c, int gk) -> float4 {
        if (c >= Ncols) return make_float4(0.f, 0.f, 0.f, 0.f);
        return *reinterpret_cast<const float4*>(B + (size_t)c * ldb + gk);
    };

    float4 rA0 = fetchA(brow + arow,      kq);
    float4 rA1 = fetchA(brow + arow + 64, kq);
    float4 rB0 = fetchB(bcol + arow,      kq);

    for (int kt = 0; kt < ktiles; kt++) {
        const int buf = kt & 1;
        As[buf][arow     ][kq+0] = __float_as_uint(rA0.x);
        As[buf][arow     ][kq+1] = __float_as_uint(rA0.y);
        As[buf][arow     ][kq+2] = __float_as_uint(rA0.z);
        As[buf][arow     ][kq+3] = __float_as_uint(rA0.w);
        As[buf][arow + 64][kq+0] = __float_as_uint(rA1.x);
        As[buf][arow + 64][kq+1] = __float_as_uint(rA1.y);
        As[buf][arow + 64][kq+2] = __float_as_uint(rA1.z);
        As[buf][arow + 64][kq+3] = __float_as_uint(rA1.w);
        if (arow < TBN) {
            Bs[buf][arow][kq+0] = __float_as_uint(rB0.x);
            Bs[buf][arow][kq+1] = __float_as_uint(rB0.y);
            Bs[buf][arow][kq+2] = __float_as_uint(rB0.z);
            Bs[buf][arow][kq+3] = __float_as_uint(rB0.w);
        }
        __syncthreads();

        if (kt + 1 < ktiles) {
            int k0 = (kt + 1) * GBK;
            rA0 = fetchA(brow + arow,      k0 + kq);
            rA1 = fetchA(brow + arow + 64, k0 + kq);
            rB0 = fetchB(bcol + arow,      k0 + kq);
        }

#pragma unroll
        for (int ks = 0; ks < 2; ks++) {
            const int kb = ks * 8;
            uint32_t af[MT][4], bf[4][2];
#pragma unroll
            for (int mt = 0; mt < MT; mt++) {
                int r0 = wm * 32 + mt * 16 + g;
                af[mt][0] = As[buf][r0    ][kb + tig];
                af[mt][1] = As[buf][r0 + 8][kb + tig];
                af[mt][2] = As[buf][r0    ][kb + tig + 4];
                af[mt][3] = As[buf][r0 + 8][kb + tig + 4];
            }
#pragma unroll
            for (int nt = 0; nt < 4; nt++) {
                int cb = wn * 32 + nt * 8 + g;
                bf[nt][0] = Bs[buf][cb][kb + tig];
                bf[nt][1] = Bs[buf][cb][kb + tig + 4];
            }
#pragma unroll
            for (int mt = 0; mt < MT; mt++)
#pragma unroll
                for (int nt = 0; nt < 4; nt++)
                    mma_tf32(acc[mt][nt], af[mt][0], af[mt][1], af[mt][2], af[mt][3],
                             bf[nt][0], bf[nt][1]);
        }
        __syncthreads();
    }

#pragma unroll
    for (int mt = 0; mt < MT; mt++) {
        int gr0 = brow + wm * 32 + mt * 16 + g;
        int gr1 = gr0 + 8;
#pragma unroll
        for (int nt = 0; nt < 4; nt++) {
            int gc = wn * 32 + nt * 8 + 2 * tig;
            float bx = bias[gc], by = bias[gc + 1];
            if (gr0 < M) {
                float2 v = make_float2(acc[mt][nt][0] + bx, acc[mt][nt][1] + by);
                size_t off = (size_t)(gr0 % NN) * (TT * EMBX) + (gr0 / NN) * EMBX + gc;
                *reinterpret_cast<float2*>(C + off) = v;
            }
            if (gr1 < M) {
                float2 v = make_float2(acc[mt][nt][2] + bx, acc[mt][nt][3] + by);
                size_t off = (size_t)(gr1 % NN) * (TT * EMBX) + (gr1 / NN) * EMBX + gc;
                *reinterpret_cast<float2*>(C + off) = v;
            }
        }
    }
}

// ---------------- host side ----------------
static inline void launch_gemm(int M, int Ncols, int K,
                               const float* A, int lda, const float* B, int ldb,
                               const float* bias, const float* addmat, int addld,
                               float* C, int ldc, int oproj)
{
    if (Ncols == 64) {
        dim3 grid((M + GBM - 1) / GBM, 1);
        gemm_tc_kernel<64><<<grid, 256>>>(M, Ncols, K, A, lda, B, ldb, bias,
                                          addmat, addld, C, ldc, oproj);
    } else {
        dim3 grid((M + GBM - 1) / GBM, (Ncols + 127) / 128);
        gemm_tc_kernel<128><<<grid, 256>>>(M, Ncols, K, A, lda, B, ldb, bias,
                                           addmat, addld, C, ldc, oproj);
    }
}

extern "C" void kernel_launch(void* const* d_in, const int* in_sizes, int n_in,
                              void* d_out, int out_size)
{
    const float* x_static = (const float*)d_in[0];
    const float* dyn      = (const float*)d_in[1];
    const int*   ei       = (const int*)  d_in[2];
    const float* W_ih     = (const float*)d_in[3];
    const float* W_hh     = (const float*)d_in[4];
    const float* b_ih     = (const float*)d_in[5];
    const float* b_hh     = (const float*)d_in[6];
    const float* Wl1      = (const float*)d_in[7];
    const float* Wr1      = (const float*)d_in[8];
    const float* att1     = (const float*)d_in[9];
    const float* bg1      = (const float*)d_in[10];
    const float* Wl2      = (const float*)d_in[11];
    const float* Wr2      = (const float*)d_in[12];
    const float* att2     = (const float*)d_in[13];
    const float* bg2      = (const float*)d_in[14];
    const float* gamma1   = (const float*)d_in[15];
    const float* beta1    = (const float*)d_in[16];
    const float* gamma2   = (const float*)d_in[17];
    const float* beta2    = (const float*)d_in[18];
    const float* Wp       = (const float*)d_in[19];
    const float* bp       = (const float*)d_in[20];
    float* out = (float*)d_out;

    void* p;
    cudaGetSymbolAddress(&p, g_hs);     float*  hs    = (float*)p;
    cudaGetSymbolAddress(&p, g_hsh);    __half* hsh   = (__half*)p;
    cudaGetSymbolAddress(&p, g_AB);     float*  AB    = (float*)p;
    cudaGetSymbolAddress(&p, g_bufC);   float*  bC    = (float*)p;
    cudaGetSymbolAddress(&p, g_bufDh);  __half* bDh   = (__half*)p;
    cudaGetSymbolAddress(&p, g_xscat);  float*  xsc   = (float*)p;
    cudaGetSymbolAddress(&p, g_gate);   float*  gate  = (float*)p;
    cudaGetSymbolAddress(&p, g_gatesx); float*  gx    = (float*)p;
    cudaGetSymbolAddress(&p, g_dynt);   float*  dynt  = (float*)p;
    cudaGetSymbolAddress(&p, g_xst);    float*  xst   = (float*)p;
    cudaGetSymbolAddress(&p, g_WcatS);  float*  WcS   = (float*)p;
    cudaGetSymbolAddress(&p, g_WcDh);   __half* WcDh  = (__half*)p;
    cudaGetSymbolAddress(&p, g_Wc2h);   __half* Wc2h  = (__half*)p;
    cudaGetSymbolAddress(&p, g_Wih);    float*  Wih   = (float*)p;
    cudaGetSymbolAddress(&p, g_Whh);    float*  Whh   = (float*)p;
    cudaGetSymbolAddress(&p, g_Wpt);    float*  Wpt   = (float*)p;
    cudaGetSymbolAddress(&p, g_bsum);   float*  bsum  = (float*)p;

    // (1) fused setup
    setup_kernel<<<(XLD * HCX + 255) / 256, 256>>>(b_ih, b_hh, Wl1, Wr1, Wl2, Wr2,
                                                   W_ih, W_hh, Wp);
    // (2) tf32 input conversions
    cvt_inputs_kernel<<<(TNN * DDIM + 255) / 256, 256>>>(dyn, x_static);

    // (3) LSTM input-side gates for all (n,t) in one GEMM
    launch_gemm(TNN, 4 * HLX, DDIM, dynt, DDIM, Wih, DDIM,
                bsum, 0, 0, gx, 4 * HLX, 0);

    // (4..) LSTM recurrence (tf32 path; gate kernel writes fp32+fp16 h)
    lstm_gate_kernel<<<(NN * HLX + 255) / 256, 256>>>(gate, 0, 1);
    for (int t = 1; t < TT; t++) {
        launch_gemm(NN, 4 * HLX, HLX, hs + (size_t)(t - 1) * NN * HLX, HLX, Whh, HLX,
                    0, 0, 0, gate, 4 * HLX, 0);
        lstm_gate_kernel<<<(NN * HLX + 255) / 256, 256>>>(gate, t, 0);
    }

    // --- CSR build
    count_kernel<<<(EE + 255) / 256, 256>>>(ei);
    scan_kernel<<<1, 1024>>>();
    fill_kernel<<<(ETOT + 255) / 256, 256>>>(ei);

    // --- static projection (combined xl|xr, constant across t)
    launch_gemm(NN, XLD, DSX, xst, DSX, WcS, DSX,
                0, 0, 0, xsc, XLD, 0);

    // --- layer 1 (fp16 GEMM): AB = hsh @ WcDh^T + xsc[r%NN]
    {
        dim3 grid(TNN / GBM, XLD / GBM);
        gemm_h_kernel<<<grid, 256>>>(TNN, XLD, HLX, hsh, HLX, WcDh, HLX,
                                     xsc, XLD, AB, XLD);
    }
    gat_kernel<<<dim3(NN, TT), 128>>>(AB, att1, bg1, bC);

    bn_stats_kernel<<<dim3((NN + BN_ROWS - 1) / BN_ROWS, TT), 256>>>(bC);
    bn_finalize_kernel<<<TT, 512>>>(gamma1, beta1);
    bn_apply_kernel<<<(TNN * HCX / 4 + 255) / 256, 256>>>(bC, bDh);

    // --- layer 2 (fp16 GEMM)
    {
        dim3 grid(TNN / GBM, XLD / GBM);
        gemm_h_kernel<<<grid, 256>>>(TNN, XLD, HCX, bDh, HCX, Wc2h, HCX,
                                     0, 0, AB, XLD);
    }
    gat_kernel<<<dim3(NN, TT), 128>>>(AB, att2, bg2, bC);

    bn_stats_kernel<<<dim3((NN + BN_ROWS - 1) / BN_ROWS, TT), 256>>>(bC);
    bn_finalize_kernel<<<TT, 512>>>(gamma2, beta2);

    // --- projection: BN2+relu fused into A-fetch, output remapped [N,T,EMB]
    gemm_proj_kernel<<<(TNN + GBM - 1) / GBM, 256>>>(TNN, EMBX, HCX,
                                                     bC, HCX, Wpt, HCX, bp, out);
}